// round 1
// baseline (speedup 1.0000x reference)
#include <cuda_runtime.h>

#define BATCH 128
#define NWALK 64
#define LWALK 32
#define TD 108
#define PD 19
#define FDIM 128
#define MDIM 128

// scratch: walk embeddings after Wl:  [s][b][nw][128]  (8 MB)
__device__ float g_emb[2 * BATCH * NWALK * MDIM];

// ---------------------------------------------------------------------------
// Kernel 1: per-(walk, sign) self-attention over L=32, D=128, fused Wl+bl.
// grid = B*NW*2 blocks, 256 threads.
// out = coef . V  with coef[m] = sum_l softmax(q k^T / sqrt(128))[l, m]
// ---------------------------------------------------------------------------
__global__ void walk_attn_kernel(
    const float* __restrict__ timef,
    const float* __restrict__ ppf,
    const float* __restrict__ pnf,
    const float* __restrict__ weightp,
    const int*   __restrict__ signp,
    const float* __restrict__ Wq, const float* __restrict__ bq,
    const float* __restrict__ Wk, const float* __restrict__ bk,
    const float* __restrict__ Wv, const float* __restrict__ bv,
    const float* __restrict__ Wl, const float* __restrict__ bl)
{
    extern __shared__ float sm[];
    float* xT       = sm;              // [128][32]   x transposed (f-major)
    float* q        = xT + 4096;       // [32][128]
    float* kT       = q + 4096;        // [128][33]   padded: conflict-free T-write
    float* v        = kT + 4224;       // [32][128]
    float* coefpart = v + 4096;        // [8][32]
    float* coef     = coefpart + 256;  // [32]
    float* outvec   = coef + 32;       // [128]

    const int bx   = blockIdx.x;
    const int s    = bx & 1;           // 0 = positive, 1 = negative
    const int walk = bx >> 1;
    const int b    = walk >> 6;        // / NWALK
    const int nw   = walk & 63;
    const int tid  = threadIdx.x;

    // ---- build features: x[l][f] = [pos_sel(19) | time(108) | weight(1)] ----
    const int wbase = (b * NWALK + nw) * LWALK;
    for (int id = tid; id < FDIM * LWALK; id += 256) {
        const int l = id & 31;
        const int f = id >> 5;
        const int e = wbase + l;
        float val;
        if (f < PD) {
            const int sg = signp[e];
            // s=0 (positive): sign>0 -> ppf else pnf ; s=1 (negative): swapped
            const bool usep = (sg > 0) != (s == 1);
            val = usep ? ppf[e * PD + f] : pnf[e * PD + f];
        } else if (f < FDIM - 1) {
            val = timef[e * TD + (f - PD)];
        } else {
            val = weightp[e];
        }
        xT[f * 32 + l] = val;
    }
    __syncthreads();

    // ---- QKV: thread (j = col, rg = 16-row group), 48 FMA per f-step ----
    {
        const int j  = tid & 127;
        const int rg = tid >> 7;      // 0..1
        float accq[16], acck[16], accv[16];
        const float bqj = bq[j], bkj = bk[j], bvj = bv[j];
        #pragma unroll
        for (int i = 0; i < 16; i++) { accq[i] = bqj; acck[i] = bkj; accv[i] = bvj; }
        const float4* xT4 = (const float4*)xT;   // [128][8]
        #pragma unroll 2
        for (int f = 0; f < FDIM; f++) {
            const float wq = Wq[f * FDIM + j];
            const float wk = Wk[f * FDIM + j];
            const float wv = Wv[f * FDIM + j];
            #pragma unroll
            for (int k4 = 0; k4 < 4; k4++) {
                const float4 xv = xT4[f * 8 + rg * 4 + k4];   // broadcast LDS.128
                accq[k4*4+0] += xv.x * wq; accq[k4*4+1] += xv.y * wq;
                accq[k4*4+2] += xv.z * wq; accq[k4*4+3] += xv.w * wq;
                acck[k4*4+0] += xv.x * wk; acck[k4*4+1] += xv.y * wk;
                acck[k4*4+2] += xv.z * wk; acck[k4*4+3] += xv.w * wk;
                accv[k4*4+0] += xv.x * wv; accv[k4*4+1] += xv.y * wv;
                accv[k4*4+2] += xv.z * wv; accv[k4*4+3] += xv.w * wv;
            }
        }
        #pragma unroll
        for (int i = 0; i < 16; i++) {
            const int r = rg * 16 + i;
            q[r * 128 + j]  = accq[i];
            kT[j * 33 + r]  = acck[i];   // banks (j+r)%32 -> conflict-free
            v[r * 128 + j]  = accv[i];
        }
    }
    __syncthreads();

    // ---- scores + softmax + column-sums (coef), all in registers/warp ----
    {
        const int m = tid & 31;          // score column = lane
        const int w = tid >> 5;          // 8 warps, rows 4w..4w+3
        float sc[4] = {0.f, 0.f, 0.f, 0.f};
        for (int f = 0; f < FDIM; f++) {
            const float kf = kT[f * 33 + m];
            #pragma unroll
            for (int i = 0; i < 4; i++)
                sc[i] += q[(4 * w + i) * 128 + f] * kf;
        }
        const float scale = 0.08838834764831845f;  // 1/sqrt(128)
        float cp = 0.f;
        #pragma unroll
        for (int i = 0; i < 4; i++) {
            float x = sc[i] * scale;
            float mx = x;
            #pragma unroll
            for (int o = 16; o > 0; o >>= 1)
                mx = fmaxf(mx, __shfl_xor_sync(0xffffffffu, mx, o));
            const float e = __expf(x - mx);
            float sme = e;
            #pragma unroll
            for (int o = 16; o > 0; o >>= 1)
                sme += __shfl_xor_sync(0xffffffffu, sme, o);
            cp += e / sme;
        }
        coefpart[w * 32 + m] = cp;
    }
    __syncthreads();
    if (tid < 32) {
        float c = 0.f;
        #pragma unroll
        for (int w = 0; w < 8; w++) c += coefpart[w * 32 + tid];
        coef[tid] = c;
    }
    __syncthreads();
    if (tid < 128) {
        float o = 0.f;
        #pragma unroll 8
        for (int m = 0; m < 32; m++) o += coef[m] * v[m * 128 + tid];
        outvec[tid] = o;
    }
    __syncthreads();
    if (tid < 128) {   // fused Wl + bl
        float r = bl[tid];
        #pragma unroll 8
        for (int f = 0; f < 128; f++) r += outvec[f] * Wl[f * 128 + tid];
        g_emb[((s * BATCH + b) * NWALK + nw) * MDIM + tid] = r;
    }
}

// ---------------------------------------------------------------------------
// Kernel 2: per-(b, sign) path attention over L=64, D=128.
// grid = 2*B blocks, 512 threads.
// ---------------------------------------------------------------------------
__global__ void path_attn_kernel(
    const float* __restrict__ Wqp, const float* __restrict__ bqp,
    const float* __restrict__ Wkp, const float* __restrict__ bkp,
    const float* __restrict__ Wvp, const float* __restrict__ bvp,
    float* __restrict__ out)
{
    extern __shared__ float sm[];
    float* xT       = sm;               // [128][64]
    float* q        = xT + 8192;        // [64][128]
    float* kT       = q + 8192;         // [128][65]
    float* v        = kT + 8320;        // [64][128]
    float* coefpart = v + 8192;         // [16][64]
    float* coef     = coefpart + 1024;  // [64]

    const int bx  = blockIdx.x;         // s*128 + b
    const int s   = bx >> 7;
    const int b   = bx & 127;
    const int tid = threadIdx.x;

    const float* x = g_emb + ((size_t)(s * BATCH + b) * NWALK) * MDIM;

    for (int id = tid; id < 64 * 128; id += 512) {
        const int l = id & 63;
        const int d = id >> 6;
        xT[d * 64 + l] = x[l * 128 + d];   // g_emb is L2-hot, tiny cost
    }
    __syncthreads();

    // ---- QKV ----
    {
        const int j  = tid & 127;
        const int rg = tid >> 7;       // 0..3, rows rg*16..+15
        float accq[16], acck[16], accv[16];
        const float bqj = bqp[j], bkj = bkp[j], bvj = bvp[j];
        #pragma unroll
        for (int i = 0; i < 16; i++) { accq[i] = bqj; acck[i] = bkj; accv[i] = bvj; }
        const float4* xT4 = (const float4*)xT;   // [128][16]
        #pragma unroll 2
        for (int f = 0; f < FDIM; f++) {
            const float wq = Wqp[f * FDIM + j];
            const float wk = Wkp[f * FDIM + j];
            const float wv = Wvp[f * FDIM + j];
            #pragma unroll
            for (int k4 = 0; k4 < 4; k4++) {
                const float4 xv = xT4[f * 16 + rg * 4 + k4];
                accq[k4*4+0] += xv.x * wq; accq[k4*4+1] += xv.y * wq;
                accq[k4*4+2] += xv.z * wq; accq[k4*4+3] += xv.w * wq;
                acck[k4*4+0] += xv.x * wk; acck[k4*4+1] += xv.y * wk;
                acck[k4*4+2] += xv.z * wk; acck[k4*4+3] += xv.w * wk;
                accv[k4*4+0] += xv.x * wv; accv[k4*4+1] += xv.y * wv;
                accv[k4*4+2] += xv.z * wv; accv[k4*4+3] += xv.w * wv;
            }
        }
        #pragma unroll
        for (int i = 0; i < 16; i++) {
            const int r = rg * 16 + i;
            q[r * 128 + j]  = accq[i];
            kT[j * 65 + r]  = acck[i];
            v[r * 128 + j]  = accv[i];
        }
    }
    __syncthreads();

    // ---- scores + softmax + coef (rows of 64: 2 columns per lane) ----
    {
        const int m = tid & 31;
        const int w = tid >> 5;          // 16 warps, rows 4w..4w+3
        float sc0[4] = {0.f,0.f,0.f,0.f};
        float sc1[4] = {0.f,0.f,0.f,0.f};
        for (int f = 0; f < FDIM; f++) {
            const float kf0 = kT[f * 65 + m];
            const float kf1 = kT[f * 65 + m + 32];
            #pragma unroll
            for (int i = 0; i < 4; i++) {
                const float qf = q[(4 * w + i) * 128 + f];
                sc0[i] += qf * kf0;
                sc1[i] += qf * kf1;
            }
        }
        const float scale = 0.08838834764831845f;
        float cp0 = 0.f, cp1 = 0.f;
        #pragma unroll
        for (int i = 0; i < 4; i++) {
            float x0 = sc0[i] * scale;
            float x1 = sc1[i] * scale;
            float mx = fmaxf(x0, x1);
            #pragma unroll
            for (int o = 16; o > 0; o >>= 1)
                mx = fmaxf(mx, __shfl_xor_sync(0xffffffffu, mx, o));
            const float e0 = __expf(x0 - mx);
            const float e1 = __expf(x1 - mx);
            float sme = e0 + e1;
            #pragma unroll
            for (int o = 16; o > 0; o >>= 1)
                sme += __shfl_xor_sync(0xffffffffu, sme, o);
            const float inv = 1.f / sme;
            cp0 += e0 * inv;
            cp1 += e1 * inv;
        }
        coefpart[w * 64 + m]      = cp0;
        coefpart[w * 64 + m + 32] = cp1;
    }
    __syncthreads();
    if (tid < 64) {
        float c = 0.f;
        #pragma unroll
        for (int w = 0; w < 16; w++) c += coefpart[w * 64 + tid];
        coef[tid] = c;
    }
    __syncthreads();
    if (tid < 128) {
        float o = 0.f;
        #pragma unroll 8
        for (int m = 0; m < 64; m++) o += coef[m] * v[m * 128 + tid];
        out[(size_t)(s * BATCH + b) * MDIM + tid] = o;   // pos block then neg block
    }
}

// ---------------------------------------------------------------------------
extern "C" void kernel_launch(void* const* d_in, const int* in_sizes, int n_in,
                              void* d_out, int out_size)
{
    const float* timef   = (const float*)d_in[0];
    const float* ppf     = (const float*)d_in[1];
    const float* pnf     = (const float*)d_in[2];
    const float* weightp = (const float*)d_in[3];
    const int*   signp   = (const int*)  d_in[4];
    const float* Wq  = (const float*)d_in[5];  const float* bq  = (const float*)d_in[6];
    const float* Wk  = (const float*)d_in[7];  const float* bk  = (const float*)d_in[8];
    const float* Wv  = (const float*)d_in[9];  const float* bv  = (const float*)d_in[10];
    const float* Wl  = (const float*)d_in[11]; const float* bl  = (const float*)d_in[12];
    const float* Wqp = (const float*)d_in[13]; const float* bqp = (const float*)d_in[14];
    const float* Wkp = (const float*)d_in[15]; const float* bkp = (const float*)d_in[16];
    const float* Wvp = (const float*)d_in[17]; const float* bvp = (const float*)d_in[18];
    float* out = (float*)d_out;

    const int smem1 = (4096 + 4096 + 4224 + 4096 + 256 + 32 + 128) * (int)sizeof(float); // 67712
    const int smem2 = (8192 + 8192 + 8320 + 8192 + 1024 + 64) * (int)sizeof(float);      // 135936

    cudaFuncSetAttribute(walk_attn_kernel, cudaFuncAttributeMaxDynamicSharedMemorySize, smem1);
    cudaFuncSetAttribute(path_attn_kernel, cudaFuncAttributeMaxDynamicSharedMemorySize, smem2);

    walk_attn_kernel<<<BATCH * NWALK * 2, 256, smem1>>>(
        timef, ppf, pnf, weightp, signp, Wq, bq, Wk, bk, Wv, bv, Wl, bl);
    path_attn_kernel<<<2 * BATCH, 512, smem2>>>(
        Wqp, bqp, Wkp, bkp, Wvp, bvp, out);
}